// round 1
// baseline (speedup 1.0000x reference)
#include <cuda_runtime.h>
#include <cstdint>
#include <cstddef>

#define CH 64
#define MAX_ENT 100000

__device__ float g_counts[MAX_ENT];
__device__ int g_is64;

// ---------------------------------------------------------------------------
// Detect whether edge buffers are int64 or int32. edge_type values are in
// [2, 18). If the buffer is really int32, reading 8 bytes gives v0 | v1<<32
// which is >= 2^32 (v1 in [2,18), never 0). Deterministic.
// ---------------------------------------------------------------------------
__global__ void detect_kernel(const void* __restrict__ edge_type) {
    long long v = ((const long long*)edge_type)[0];
    g_is64 = (v >= 2 && v < 64) ? 1 : 0;
}

// ---------------------------------------------------------------------------
// KG aggregate: 16 threads per edge; thread s handles float4 slice s of the
// 64-float channel. Gather entity_emb[tail] * weight[type-2], vector-RED
// into ent_out[head]. Lane s==0 bumps the per-head count.
// ---------------------------------------------------------------------------
__global__ void __launch_bounds__(256) edge_kernel(
    const void* __restrict__ edge_index, const void* __restrict__ edge_type,
    const float* __restrict__ entity_emb, const float* __restrict__ weight,
    float* __restrict__ ent_out, int E)
{
    int t = blockIdx.x * 256 + threadIdx.x;
    int e = t >> 4;
    if (e >= E) return;
    int s = t & 15;

    int head, tail, rel;
    if (g_is64) {
        const long long* ei = (const long long*)edge_index;
        head = (int)ei[e];
        tail = (int)ei[(size_t)E + e];
        rel  = (int)((const long long*)edge_type)[e] - 2;
    } else {
        const int* ei = (const int*)edge_index;
        head = ei[e];
        tail = ei[(size_t)E + e];
        rel  = ((const int*)edge_type)[e] - 2;
    }

    float4 a = ((const float4*)(entity_emb + (size_t)tail * CH))[s];
    float4 w = ((const float4*)(weight + (size_t)rel * CH))[s];
    float4 v = make_float4(a.x * w.x, a.y * w.y, a.z * w.z, a.w * w.w);

    float* dst = ent_out + (size_t)head * CH + s * 4;
    asm volatile("red.global.add.v4.f32 [%0], {%1,%2,%3,%4};"
                 :: "l"(dst), "f"(v.x), "f"(v.y), "f"(v.z), "f"(v.w)
                 : "memory");

    if (s == 0) atomicAdd(&g_counts[head], 1.0f);
}

// ---------------------------------------------------------------------------
// Divide each entity row by max(count, 1). One thread per float4.
// ---------------------------------------------------------------------------
__global__ void __launch_bounds__(256) finalize_kernel(
    float* __restrict__ ent_out, int n_ent)
{
    int i = blockIdx.x * 256 + threadIdx.x;   // float4 index
    int total = n_ent * (CH / 4);
    if (i >= total) return;
    int ent = i >> 4;
    float inv = 1.0f / fmaxf(g_counts[ent], 1.0f);
    float4 v = ((const float4*)ent_out)[i];
    v.x *= inv; v.y *= inv; v.z *= inv; v.w *= inv;
    ((float4*)ent_out)[i] = v;
}

// ---------------------------------------------------------------------------
// out[r, :] = 2 * (mat[r, :] @ A)   for A = aspect_emb [64,64].
// (softmax row-sum == 1, so score-weighted term == plain term: factor 2.)
// 64 rows per block, 256 threads: thread (r = tid/4, q = tid%4) computes
// 16 output columns [q*16, q*16+16). sM padded to 65 floats/row to avoid
// 8-way bank conflicts on the per-k broadcast read.
// ---------------------------------------------------------------------------
__global__ void __launch_bounds__(256) gemm2_kernel(
    const float* __restrict__ mat, const float* __restrict__ A,
    float* __restrict__ out, int nrows)
{
    __shared__ float sA[64 * 64];
    __shared__ float sM[64 * 65];
    int tid  = threadIdx.x;
    int row0 = blockIdx.x * 64;

    for (int i = tid; i < 4096; i += 256) sA[i] = A[i];
    for (int i = tid; i < 4096; i += 256) {
        int r = i >> 6, c = i & 63;
        int gr = row0 + r;
        sM[r * 65 + c] = (gr < nrows) ? mat[(size_t)gr * 64 + c] : 0.0f;
    }
    __syncthreads();

    int r = tid >> 2, q = tid & 3;
    float4 acc0 = {0,0,0,0}, acc1 = {0,0,0,0}, acc2 = {0,0,0,0}, acc3 = {0,0,0,0};
    const float4* sA4 = (const float4*)sA;

    #pragma unroll
    for (int k = 0; k < 64; k++) {
        float m = sM[r * 65 + k];
        float4 b0 = sA4[k * 16 + q * 4 + 0];
        float4 b1 = sA4[k * 16 + q * 4 + 1];
        float4 b2 = sA4[k * 16 + q * 4 + 2];
        float4 b3 = sA4[k * 16 + q * 4 + 3];
        acc0.x += m * b0.x; acc0.y += m * b0.y; acc0.z += m * b0.z; acc0.w += m * b0.w;
        acc1.x += m * b1.x; acc1.y += m * b1.y; acc1.z += m * b1.z; acc1.w += m * b1.w;
        acc2.x += m * b2.x; acc2.y += m * b2.y; acc2.z += m * b2.z; acc2.w += m * b2.w;
        acc3.x += m * b3.x; acc3.y += m * b3.y; acc3.z += m * b3.z; acc3.w += m * b3.w;
    }

    int gr = row0 + r;
    if (gr < nrows) {
        float4* o = (float4*)(out + (size_t)gr * 64 + q * 16);
        acc0.x *= 2.f; acc0.y *= 2.f; acc0.z *= 2.f; acc0.w *= 2.f;
        acc1.x *= 2.f; acc1.y *= 2.f; acc1.z *= 2.f; acc1.w *= 2.f;
        acc2.x *= 2.f; acc2.y *= 2.f; acc2.z *= 2.f; acc2.w *= 2.f;
        acc3.x *= 2.f; acc3.y *= 2.f; acc3.z *= 2.f; acc3.w *= 2.f;
        o[0] = acc0; o[1] = acc1; o[2] = acc2; o[3] = acc3;
    }
}

// ---------------------------------------------------------------------------
// Launch
// ---------------------------------------------------------------------------
extern "C" void kernel_launch(void* const* d_in, const int* in_sizes, int n_in,
                              void* d_out, int out_size)
{
    const float* entity_emb = (const float*)d_in[0];
    // d_in[1] (item_emb) and d_in[2] (user_emb) are provably unused:
    // softmax rows sum to 1, so their only consumer collapses to a factor 2.
    const float* aspect_emb = (const float*)d_in[3];
    const void*  edge_index = d_in[4];
    const void*  edge_type  = d_in[5];
    const float* ua_mat     = (const float*)d_in[6];
    const float* ia_mat     = (const float*)d_in[7];
    const float* weight     = (const float*)d_in[8];

    int n_ent   = in_sizes[0] / CH;
    int n_users = in_sizes[6] / CH;
    int n_items = in_sizes[7] / CH;
    int E       = in_sizes[5];

    float* out      = (float*)d_out;
    float* item_out = out;
    float* ent_out  = out + (size_t)n_items * CH;
    float* user_out = ent_out + (size_t)n_ent * CH;

    void* counts_ptr = nullptr;
    cudaGetSymbolAddress(&counts_ptr, g_counts);

    // Zero accumulators (graph-capturable async memsets).
    cudaMemsetAsync(ent_out, 0, (size_t)n_ent * CH * sizeof(float));
    cudaMemsetAsync(counts_ptr, 0, (size_t)n_ent * sizeof(float));

    detect_kernel<<<1, 1>>>(edge_type);

    int eblocks = (E * 16 + 255) / 256;
    edge_kernel<<<eblocks, 256>>>(edge_index, edge_type, entity_emb, weight,
                                  ent_out, E);

    finalize_kernel<<<(n_ent * (CH / 4) + 255) / 256, 256>>>(ent_out, n_ent);

    gemm2_kernel<<<(n_items + 63) / 64, 256>>>(ia_mat, aspect_emb, item_out, n_items);
    gemm2_kernel<<<(n_users + 63) / 64, 256>>>(ua_mat, aspect_emb, user_out, n_users);
}

// round 2
// speedup vs baseline: 1.9672x; 1.9672x over previous
#include <cuda_runtime.h>
#include <cstdint>
#include <cstddef>

#define CH 64
#define MAX_ENT 100000
#define BR 256          // rows per gemm block

__device__ float g_counts[MAX_ENT];
__device__ int g_is64;

// ---------------------------------------------------------------------------
// Detect int64 vs int32 edge buffers. edge_type values are in [2,18); an
// 8-byte read of an int32 buffer is >= 2^32. Deterministic.
// ---------------------------------------------------------------------------
__global__ void detect_kernel(const void* __restrict__ edge_type) {
    long long v = ((const long long*)edge_type)[0];
    g_is64 = (v >= 2 && v < 64) ? 1 : 0;
}

// ---------------------------------------------------------------------------
// KG aggregate: 16 threads/edge, thread s handles float4 slice s.
// gather entity_emb[tail]*weight[rel], vector-RED into ent_out[head].
// ---------------------------------------------------------------------------
__global__ void __launch_bounds__(256) edge_kernel(
    const void* __restrict__ edge_index, const void* __restrict__ edge_type,
    const float* __restrict__ entity_emb, const float* __restrict__ weight,
    float* __restrict__ ent_out, int E)
{
    int t = blockIdx.x * 256 + threadIdx.x;
    int e = t >> 4;
    if (e >= E) return;
    int s = t & 15;

    int head, tail, rel;
    if (g_is64) {
        const long long* ei = (const long long*)edge_index;
        head = (int)ei[e];
        tail = (int)ei[(size_t)E + e];
        rel  = (int)((const long long*)edge_type)[e] - 2;
    } else {
        const int* ei = (const int*)edge_index;
        head = ei[e];
        tail = ei[(size_t)E + e];
        rel  = ((const int*)edge_type)[e] - 2;
    }

    float4 a = ((const float4*)(entity_emb + (size_t)tail * CH))[s];
    float4 w = ((const float4*)(weight + (size_t)rel * CH))[s];
    float4 v = make_float4(a.x * w.x, a.y * w.y, a.z * w.z, a.w * w.w);

    float* dst = ent_out + (size_t)head * CH + s * 4;
    asm volatile("red.global.add.v4.f32 [%0], {%1,%2,%3,%4};"
                 :: "l"(dst), "f"(v.x), "f"(v.y), "f"(v.z), "f"(v.w)
                 : "memory");

    if (s == 0) atomicAdd(&g_counts[head], 1.0f);
}

// ---------------------------------------------------------------------------
// Divide each entity row by max(count, 1).
// ---------------------------------------------------------------------------
__global__ void __launch_bounds__(256) finalize_kernel(
    float* __restrict__ ent_out, int n_ent)
{
    int i = blockIdx.x * 256 + threadIdx.x;   // float4 index
    int total = n_ent * (CH / 4);
    if (i >= total) return;
    int ent = i >> 4;
    float inv = 1.0f / fmaxf(g_counts[ent], 1.0f);
    float4 v = ((const float4*)ent_out)[i];
    v.x *= inv; v.y *= inv; v.z *= inv; v.w *= inv;
    ((float4*)ent_out)[i] = v;
}

// ---------------------------------------------------------------------------
// Fused GEMMs: out = 2*(mat @ A) for both ia_mat and ua_mat (softmax row-sum
// == 1 collapses the score term to a factor of 2).
//
// 256 rows/block, 256 threads. Thread (g=tid/4, q=tid&3) computes rows
// [4g,4g+4) x cols [16q,16q+16), accumulating in packed f32x2 registers via
// fma.rn.f32x2 (FFMA2: 2x fp32 throughput, PTX-only on sm_103a).
//
// A staged bank-permuted: sA[k][j*4+q] holds original float4 (cols q*16+j*4),
// so a warp phase (q=0..3) reads 4 consecutive 16B chunks -> conflict-free.
// sM rows padded to 68 floats (17 float4) -> conflict-free m loads.
// LDS bytes amortized over 4 rows/thread: ~5 LDS.128 per 32 FFMA2.
// ---------------------------------------------------------------------------
__global__ void __launch_bounds__(256, 2) gemm_fused_kernel(
    const float* __restrict__ ia, int n_items,
    const float* __restrict__ ua, int n_users,
    const float* __restrict__ A,
    float* __restrict__ item_out, float* __restrict__ user_out,
    int item_blocks)
{
    extern __shared__ float sm[];
    float* sA = sm;              // 64*64 floats, permuted
    float* sM = sm + 4096;       // 256 rows x 68 floats

    const float* mat; float* out; int nrows; int row0;
    if ((int)blockIdx.x < item_blocks) {
        mat = ia; out = item_out; nrows = n_items; row0 = blockIdx.x * BR;
    } else {
        mat = ua; out = user_out; nrows = n_users;
        row0 = (blockIdx.x - item_blocks) * BR;
    }

    int tid = threadIdx.x;

    // Stage A with within-row permutation c' = (c&3)*4 + (c>>2)  (c = float4 idx)
    const float4* A4 = (const float4*)A;
    float4* sA4 = (float4*)sA;
    for (int idx = tid; idx < 1024; idx += 256) {
        int k = idx >> 4, c = idx & 15;
        sA4[k * 16 + ((c & 3) << 2) + (c >> 2)] = A4[idx];
    }
    // Stage M tile (zero-padded), row stride 17 float4
    float4* sM4 = (float4*)sM;
    const float4* mat4 = (const float4*)mat;
    for (int idx = tid; idx < 4096; idx += 256) {
        int r = idx >> 4, c = idx & 15;
        int gr = row0 + r;
        float4 v = make_float4(0.f, 0.f, 0.f, 0.f);
        if (gr < nrows) v = mat4[(size_t)gr * 16 + c];
        sM4[r * 17 + c] = v;
    }
    __syncthreads();

    int g = tid >> 2, q = tid & 3;
    unsigned long long acc[4][8];
    #pragma unroll
    for (int i = 0; i < 4; i++)
        #pragma unroll
        for (int p = 0; p < 8; p++) acc[i][p] = 0ull;

    const ulonglong2* sA8 = (const ulonglong2*)sA;

    for (int kk = 0; kk < 16; kk++) {
        float4 mv[4];
        #pragma unroll
        for (int i = 0; i < 4; i++) mv[i] = sM4[(4 * g + i) * 17 + kk];

        #pragma unroll
        for (int u = 0; u < 4; u++) {
            int k = kk * 4 + u;
            ulonglong2 b[4];
            #pragma unroll
            for (int j = 0; j < 4; j++) b[j] = sA8[k * 16 + j * 4 + q];

            #pragma unroll
            for (int i = 0; i < 4; i++) {
                float mu = (u == 0) ? mv[i].x : (u == 1) ? mv[i].y
                         : (u == 2) ? mv[i].z : mv[i].w;
                unsigned long long m2;
                asm("mov.b64 %0, {%1, %1};" : "=l"(m2) : "f"(mu));
                #pragma unroll
                for (int j = 0; j < 4; j++) {
                    asm("fma.rn.f32x2 %0, %1, %2, %0;"
                        : "+l"(acc[i][2 * j])     : "l"(b[j].x), "l"(m2));
                    asm("fma.rn.f32x2 %0, %1, %2, %0;"
                        : "+l"(acc[i][2 * j + 1]) : "l"(b[j].y), "l"(m2));
                }
            }
        }
    }

    int gr0 = row0 + 4 * g;
    #pragma unroll
    for (int i = 0; i < 4; i++) {
        int gr = gr0 + i;
        if (gr < nrows) {
            ulonglong2* o = (ulonglong2*)(out + (size_t)gr * CH + q * 16);
            #pragma unroll
            for (int p = 0; p < 4; p++) {
                unsigned long long d0, d1;
                asm("add.rn.f32x2 %0, %1, %1;" : "=l"(d0) : "l"(acc[i][2 * p]));
                asm("add.rn.f32x2 %0, %1, %1;" : "=l"(d1) : "l"(acc[i][2 * p + 1]));
                ulonglong2 d; d.x = d0; d.y = d1;
                o[p] = d;
            }
        }
    }
}

// ---------------------------------------------------------------------------
// Launch
// ---------------------------------------------------------------------------
extern "C" void kernel_launch(void* const* d_in, const int* in_sizes, int n_in,
                              void* d_out, int out_size)
{
    const float* entity_emb = (const float*)d_in[0];
    const float* aspect_emb = (const float*)d_in[3];
    const void*  edge_index = d_in[4];
    const void*  edge_type  = d_in[5];
    const float* ua_mat     = (const float*)d_in[6];
    const float* ia_mat     = (const float*)d_in[7];
    const float* weight     = (const float*)d_in[8];

    int n_ent   = in_sizes[0] / CH;
    int n_users = in_sizes[6] / CH;
    int n_items = in_sizes[7] / CH;
    int E       = in_sizes[5];

    float* out      = (float*)d_out;
    float* item_out = out;
    float* ent_out  = out + (size_t)n_items * CH;
    float* user_out = ent_out + (size_t)n_ent * CH;

    void* counts_ptr = nullptr;
    cudaGetSymbolAddress(&counts_ptr, g_counts);

    cudaMemsetAsync(ent_out, 0, (size_t)n_ent * CH * sizeof(float));
    cudaMemsetAsync(counts_ptr, 0, (size_t)n_ent * sizeof(float));

    detect_kernel<<<1, 1>>>(edge_type);

    int eblocks = (E * 16 + 255) / 256;
    edge_kernel<<<eblocks, 256>>>(edge_index, edge_type, entity_emb, weight,
                                  ent_out, E);

    finalize_kernel<<<(n_ent * (CH / 4) + 255) / 256, 256>>>(ent_out, n_ent);

    // Fused GEMMs (items + users) with >48KB dynamic smem
    int item_blocks = (n_items + BR - 1) / BR;
    int user_blocks = (n_users + BR - 1) / BR;
    int smem_bytes  = (4096 + BR * 68) * sizeof(float);   // 84 KB
    static int smem_set = 0;
    if (!smem_set) {
        cudaFuncSetAttribute(gemm_fused_kernel,
                             cudaFuncAttributeMaxDynamicSharedMemorySize,
                             smem_bytes);
        smem_set = 1;
    }
    gemm_fused_kernel<<<item_blocks + user_blocks, 256, smem_bytes>>>(
        ia_mat, n_items, ua_mat, n_users, aspect_emb,
        item_out, user_out, item_blocks);
}

// round 3
// speedup vs baseline: 2.2727x; 1.1553x over previous
#include <cuda_runtime.h>
#include <cstdint>
#include <cstddef>

#define CH 64
#define ENT_MAX 100000
#define E_MAX   1250000
#define GR 512          // rows per gemm block

__device__ int g_hist[ENT_MAX];     // per-head edge count
__device__ int g_off[ENT_MAX];      // exclusive CSR offsets
__device__ int g_cur[ENT_MAX];      // scatter cursors
__device__ int g_packed[E_MAX];     // tail | rel<<20, grouped by head
__device__ int g_bsum[256];         // scan block sums
__device__ int g_is64;

// ---------------------------------------------------------------------------
// int64 vs int32 edge-buffer detection (values in [2,18); an 8B read of an
// int32 buffer is >= 2^32).
// ---------------------------------------------------------------------------
__global__ void detect_kernel(const void* __restrict__ edge_type) {
    long long v = ((const long long*)edge_type)[0];
    g_is64 = (v >= 2 && v < 64) ? 1 : 0;
}

__device__ __forceinline__ void load_edge(
    const void* ei, const void* et, int e, int E, int& head, int& tail, int& rel)
{
    if (g_is64) {
        const long long* p = (const long long*)ei;
        head = (int)p[e];
        tail = (int)p[(size_t)E + e];
        rel  = (int)((const long long*)et)[e] - 2;
    } else {
        const int* p = (const int*)ei;
        head = p[e];
        tail = p[(size_t)E + e];
        rel  = ((const int*)et)[e] - 2;
    }
}

// ---------------------------------------------------------------------------
// 1) histogram of heads
// ---------------------------------------------------------------------------
__global__ void __launch_bounds__(256) hist_kernel(
    const void* __restrict__ ei, int E)
{
    int e = blockIdx.x * 256 + threadIdx.x;
    if (e >= E) return;
    int head;
    if (g_is64) head = (int)((const long long*)ei)[e];
    else        head = ((const int*)ei)[e];
    atomicAdd(&g_hist[head], 1);
}

// ---------------------------------------------------------------------------
// 2) exclusive scan of g_hist -> g_off (3 kernels, 512-wide chunks)
// ---------------------------------------------------------------------------
__global__ void __launch_bounds__(512) scan1_kernel(int n) {
    __shared__ int s[2][512];
    int t = threadIdx.x;
    int i = blockIdx.x * 512 + t;
    int v = (i < n) ? g_hist[i] : 0;
    s[0][t] = v;
    __syncthreads();
    int sb = 0;
    #pragma unroll
    for (int off = 1; off < 512; off <<= 1) {
        int x = s[sb][t];
        if (t >= off) x += s[sb][t - off];
        s[sb ^ 1][t] = x;
        sb ^= 1;
        __syncthreads();
    }
    int incl = s[sb][t];
    if (i < n) g_off[i] = incl - v;          // exclusive within chunk
    if (t == 511) g_bsum[blockIdx.x] = incl; // chunk total
}

__global__ void __launch_bounds__(256) scan2_kernel(int nchunk) {
    __shared__ int s[2][256];
    int t = threadIdx.x;
    int v = (t < nchunk) ? g_bsum[t] : 0;
    s[0][t] = v;
    __syncthreads();
    int sb = 0;
    #pragma unroll
    for (int off = 1; off < 256; off <<= 1) {
        int x = s[sb][t];
        if (t >= off) x += s[sb][t - off];
        s[sb ^ 1][t] = x;
        sb ^= 1;
        __syncthreads();
    }
    g_bsum[t] = s[sb][t] - v;                // exclusive chunk offsets
}

__global__ void __launch_bounds__(256) scan3_kernel(int n) {
    int i = blockIdx.x * 256 + threadIdx.x;
    if (i >= n) return;
    int o = g_off[i] + g_bsum[i >> 9];
    g_off[i] = o;
    g_cur[i] = o;
}

// ---------------------------------------------------------------------------
// 3) scatter edges into CSR order (packed tail | rel<<20)
// ---------------------------------------------------------------------------
__global__ void __launch_bounds__(256) scatter_kernel(
    const void* __restrict__ ei, const void* __restrict__ et, int E)
{
    int e = blockIdx.x * 256 + threadIdx.x;
    if (e >= E) return;
    int head, tail, rel;
    load_edge(ei, et, e, E, head, tail, rel);
    int pos = atomicAdd(&g_cur[head], 1);
    g_packed[pos] = tail | (rel << 20);
}

// ---------------------------------------------------------------------------
// 4) segment mean: one warp per head. Lane l owns channels [2l, 2l+2) as a
// packed f32x2. Gathers entity row (fully coalesced 256B) * weight row
// (L1-resident, 4KB table) with fma.rn.f32x2, writes mean once.
// ---------------------------------------------------------------------------
__global__ void __launch_bounds__(256) seg_kernel(
    const float* __restrict__ entity_emb, const float* __restrict__ weight,
    float* __restrict__ ent_out, int n_ent)
{
    int warp = (blockIdx.x * 256 + threadIdx.x) >> 5;
    if (warp >= n_ent) return;
    int lane = threadIdx.x & 31;

    int start = g_off[warp];
    int n     = g_hist[warp];

    const unsigned long long* ent8 = (const unsigned long long*)entity_emb;
    const unsigned long long* w8   = (const unsigned long long*)weight;

    unsigned long long acc = 0ull;
    int i = 0;
    for (; i + 2 <= n; i += 2) {
        int p0 = g_packed[start + i];
        int p1 = g_packed[start + i + 1];
        unsigned long long e0 = ent8[(size_t)(p0 & 0xFFFFF) * 32 + lane];
        unsigned long long w0 = w8[(size_t)(p0 >> 20) * 32 + lane];
        unsigned long long e1 = ent8[(size_t)(p1 & 0xFFFFF) * 32 + lane];
        unsigned long long w1 = w8[(size_t)(p1 >> 20) * 32 + lane];
        asm("fma.rn.f32x2 %0, %1, %2, %0;" : "+l"(acc) : "l"(e0), "l"(w0));
        asm("fma.rn.f32x2 %0, %1, %2, %0;" : "+l"(acc) : "l"(e1), "l"(w1));
    }
    if (i < n) {
        int p0 = g_packed[start + i];
        unsigned long long e0 = ent8[(size_t)(p0 & 0xFFFFF) * 32 + lane];
        unsigned long long w0 = w8[(size_t)(p0 >> 20) * 32 + lane];
        asm("fma.rn.f32x2 %0, %1, %2, %0;" : "+l"(acc) : "l"(e0), "l"(w0));
    }

    float inv = 1.0f / (float)max(n, 1);
    float2 a;
    asm("mov.b64 {%0, %1}, %2;" : "=f"(a.x), "=f"(a.y) : "l"(acc));
    a.x *= inv; a.y *= inv;
    ((float2*)(ent_out + (size_t)warp * CH))[lane] = a;
}

// ---------------------------------------------------------------------------
// Fused GEMMs: out = 2*(mat @ A). 512 rows/block, 512 threads.
// Thread (g=tid>>3, q=tid&7) computes rows {g+64i} x cols [8q, 8q+8).
// A permuted so fixed-j reads are contiguous 128B broadcasts; sM row stride
// 17 float4 puts the 4 distinct g-addresses on disjoint banks.
// ---------------------------------------------------------------------------
__global__ void __launch_bounds__(512, 1) gemm_fused_kernel(
    const float* __restrict__ ia, int n_items,
    const float* __restrict__ ua, int n_users,
    const float* __restrict__ A,
    float* __restrict__ item_out, float* __restrict__ user_out,
    int item_blocks)
{
    extern __shared__ float sm[];
    float*  sA  = sm;                       // 64x64, permuted
    float4* sM4 = (float4*)(sm + 4096);     // 512 rows x 17 float4

    const float* mat; float* out; int nrows; int row0;
    if ((int)blockIdx.x < item_blocks) {
        mat = ia; out = item_out; nrows = n_items; row0 = blockIdx.x * GR;
    } else {
        mat = ua; out = user_out; nrows = n_users;
        row0 = (blockIdx.x - item_blocks) * GR;
    }

    int tid = threadIdx.x;

    // Stage A: chunk c (float4 idx in row) -> permuted (c&1)*8 + (c>>1)
    const float4* A4 = (const float4*)A;
    float4* sA4 = (float4*)sA;
    for (int idx = tid; idx < 1024; idx += 512) {
        int k = idx >> 4, c = idx & 15;
        sA4[k * 16 + ((c & 1) << 3) + (c >> 1)] = A4[idx];
    }
    // Stage M tile, zero-padded, row stride 17 float4
    const float4* mat4 = (const float4*)mat;
    for (int idx = tid; idx < GR * 16; idx += 512) {
        int r = idx >> 4, c = idx & 15;
        int gr = row0 + r;
        float4 v = make_float4(0.f, 0.f, 0.f, 0.f);
        if (gr < nrows) v = mat4[(size_t)gr * 16 + c];
        sM4[r * 17 + c] = v;
    }
    __syncthreads();

    int g = tid >> 3, q = tid & 7;
    unsigned long long acc[8][4];
    #pragma unroll
    for (int i = 0; i < 8; i++)
        #pragma unroll
        for (int p = 0; p < 4; p++) acc[i][p] = 0ull;

    const ulonglong2* sA8 = (const ulonglong2*)sA;

    for (int kk = 0; kk < 16; kk++) {
        float4 mv[8];
        #pragma unroll
        for (int i = 0; i < 8; i++) mv[i] = sM4[(g + 64 * i) * 17 + kk];

        #pragma unroll
        for (int u = 0; u < 4; u++) {
            int k = kk * 4 + u;
            ulonglong2 b0 = sA8[k * 16 + q];
            ulonglong2 b1 = sA8[k * 16 + 8 + q];
            #pragma unroll
            for (int i = 0; i < 8; i++) {
                float mu = (u == 0) ? mv[i].x : (u == 1) ? mv[i].y
                         : (u == 2) ? mv[i].z : mv[i].w;
                unsigned long long m2;
                asm("mov.b64 %0, {%1, %1};" : "=l"(m2) : "f"(mu));
                asm("fma.rn.f32x2 %0, %1, %2, %0;" : "+l"(acc[i][0]) : "l"(b0.x), "l"(m2));
                asm("fma.rn.f32x2 %0, %1, %2, %0;" : "+l"(acc[i][1]) : "l"(b0.y), "l"(m2));
                asm("fma.rn.f32x2 %0, %1, %2, %0;" : "+l"(acc[i][2]) : "l"(b1.x), "l"(m2));
                asm("fma.rn.f32x2 %0, %1, %2, %0;" : "+l"(acc[i][3]) : "l"(b1.y), "l"(m2));
            }
        }
    }

    #pragma unroll
    for (int i = 0; i < 8; i++) {
        int gr = row0 + g + 64 * i;
        if (gr < nrows) {
            ulonglong2* o = (ulonglong2*)(out + (size_t)gr * CH + q * 8);
            unsigned long long d0, d1, d2, d3;
            asm("add.rn.f32x2 %0, %1, %1;" : "=l"(d0) : "l"(acc[i][0]));
            asm("add.rn.f32x2 %0, %1, %1;" : "=l"(d1) : "l"(acc[i][1]));
            asm("add.rn.f32x2 %0, %1, %1;" : "=l"(d2) : "l"(acc[i][2]));
            asm("add.rn.f32x2 %0, %1, %1;" : "=l"(d3) : "l"(acc[i][3]));
            ulonglong2 w0; w0.x = d0; w0.y = d1;
            ulonglong2 w1; w1.x = d2; w1.y = d3;
            o[0] = w0; o[1] = w1;
        }
    }
}

// ---------------------------------------------------------------------------
// Launch
// ---------------------------------------------------------------------------
extern "C" void kernel_launch(void* const* d_in, const int* in_sizes, int n_in,
                              void* d_out, int out_size)
{
    const float* entity_emb = (const float*)d_in[0];
    const float* aspect_emb = (const float*)d_in[3];
    const void*  edge_index = d_in[4];
    const void*  edge_type  = d_in[5];
    const float* ua_mat     = (const float*)d_in[6];
    const float* ia_mat     = (const float*)d_in[7];
    const float* weight     = (const float*)d_in[8];

    int n_ent   = in_sizes[0] / CH;
    int n_users = in_sizes[6] / CH;
    int n_items = in_sizes[7] / CH;
    int E       = in_sizes[5];

    float* out      = (float*)d_out;
    float* item_out = out;
    float* ent_out  = out + (size_t)n_items * CH;
    float* user_out = ent_out + (size_t)n_ent * CH;

    void* hist_ptr = nullptr;
    cudaGetSymbolAddress(&hist_ptr, g_hist);
    cudaMemsetAsync(hist_ptr, 0, (size_t)n_ent * sizeof(int));

    detect_kernel<<<1, 1>>>(edge_type);

    // --- CSR build ---
    hist_kernel<<<(E + 255) / 256, 256>>>(edge_index, E);
    int nchunk = (n_ent + 511) / 512;
    scan1_kernel<<<nchunk, 512>>>(n_ent);
    scan2_kernel<<<1, 256>>>(nchunk);
    scan3_kernel<<<(n_ent + 255) / 256, 256>>>(n_ent);
    scatter_kernel<<<(E + 255) / 256, 256>>>(edge_index, edge_type, E);

    // --- segment mean (one warp per head; writes all rows incl. empties) ---
    seg_kernel<<<(n_ent * 32 + 255) / 256, 256>>>(entity_emb, weight,
                                                  ent_out, n_ent);

    // --- fused GEMMs ---
    int item_blocks = (n_items + GR - 1) / GR;
    int user_blocks = (n_users + GR - 1) / GR;
    int smem_bytes  = (4096 + GR * 68) * sizeof(float);   // 152 KB
    cudaFuncSetAttribute(gemm_fused_kernel,
                         cudaFuncAttributeMaxDynamicSharedMemorySize,
                         smem_bytes);
    gemm_fused_kernel<<<item_blocks + user_blocks, 512, smem_bytes>>>(
        ia_mat, n_items, ua_mat, n_users, aspect_emb,
        item_out, user_out, item_blocks);
}